// round 5
// baseline (speedup 1.0000x reference)
#include <cuda_runtime.h>
#include <cuda_bf16.h>
#include <stdint.h>

#define NN 96
#define DD 64
#define CC 30

// Scratch (__device__ globals; no allocation allowed)
__device__ float    g_mat[NN * NN];
__device__ unsigned g_smask[NN * 3];
__device__ unsigned g_dmask[NN * 3];
__device__ unsigned g_cmask[NN * NN * 4];   // 96-bit mask per (i,p), stride 4 words
__device__ unsigned g_count;                 // grid barrier (monotonic; +96 per launch)

// ---------------------------------------------------------------------------
// kAB: fused prep, 96 blocks x 1024 threads, one launch.
//  Phase 1: blocks 0..8  -> cosine mat (one output per thread; 9*1024 = 96*96)
//           blocks 9..11 -> label masks via warp ballots
//           blocks 12..95 -> straight to barrier
//  Grid barrier: monotonic counter; target = next multiple of 96. Each launch
//  adds exactly 96 arrivals -> replay-safe, deterministic.
//  Phase 2: every block = one anchor i. Redundant bit-identical epsilon
//           reduce, then 96-bit c-mask ballots for that anchor.
// ---------------------------------------------------------------------------
__global__ __launch_bounds__(1024) void kAB_prep(const float* __restrict__ logits,
                                                 const float* __restrict__ labels) {
    __shared__ float    sx[NN * 65];      // phase-1 mat tile (blocks 0..8)
    __shared__ float    rn[NN];
    __shared__ float    s_rnum[NN], s_rq[NN];
    __shared__ float    s_eps;
    __shared__ float    srow[NN];
    __shared__ unsigned sm[3], dm[3];

    const int tid  = threadIdx.x;
    const int bid  = blockIdx.x;
    const int warp = tid >> 5, lane = tid & 31;

    // ======================= Phase 1 =======================
    if (bid < 9) {
        #pragma unroll
        for (int it = 0; it < 6; it++) {
            int t = it * 1024 + tid;                  // 6144 = 96*64
            sx[(t >> 6) * 65 + (t & 63)] = logits[t];
        }
        __syncthreads();
        if (tid < NN) {                               // norms (same order as before)
            float s = 0.f;
            #pragma unroll
            for (int d = 0; d < DD; d++) { float v = sx[tid * 65 + d]; s += v * v; }
            rn[tid] = rsqrtf(s);
        }
        __syncthreads();
        const int outp = bid * 1024 + tid;            // 0..9215
        const int r = outp / NN;                      // warp-uniform (96 = 3 warps)
        const int c = outp - r * NN;
        float acc = 0.f;
        #pragma unroll
        for (int d = 0; d < DD; d++) acc += sx[r * 65 + d] * sx[c * 65 + d];
        g_mat[outp] = -acc * rn[r] * rn[c];
    } else if (bid < 12) {
        // reuse sx as label storage (NN*CC = 2880 <= NN*65)
        #pragma unroll
        for (int it = 0; it < 3; it++) {
            int t = it * 1024 + tid;                  // 2880 = 96*30
            if (t < NN * CC) sx[t] = labels[t];
        }
        __syncthreads();
        const int i = (bid - 9) * 32 + warp;          // row 0..95
        #pragma unroll
        for (int wd = 0; wd < 3; wd++) {
            int j = wd * 32 + lane;
            float acc = 0.f;
            #pragma unroll
            for (int cc = 0; cc < CC; cc++) acc += sx[i * CC + cc] * sx[j * CC + cc];
            bool same_raw = acc > 0.f;
            unsigned sb = __ballot_sync(0xffffffffu, same_raw && (j != i));
            unsigned db = __ballot_sync(0xffffffffu, !same_raw);
            if (lane == 0) {
                g_smask[i * 3 + wd] = sb;
                g_dmask[i * 3 + wd] = db;
            }
        }
    }

    // ======================= Grid barrier =======================
    __syncthreads();
    if (tid == 0) {
        __threadfence();                              // publish phase-1 writes
        unsigned prev   = atomicAdd(&g_count, 1u);
        unsigned target = (prev / 96u + 1u) * 96u;    // end of THIS launch's wave
        while (*(volatile unsigned*)&g_count < target) { }
        __threadfence();                              // acquire phase-1 writes
    }
    __syncthreads();

    // ======================= Phase 2 =======================
    const int ianc = bid;

    // epsilon: identical math/order in every block -> deterministic
    for (int i = warp; i < NN; i += 32) {
        float S = 0.f, ds = 0.f, ms = 0.f, md = 0.f;
        #pragma unroll
        for (int jj = 0; jj < 3; jj++) {
            float mv = g_mat[i * NN + jj * 32 + lane];
            if ((g_smask[i * 3 + jj] >> lane) & 1u) { S += 1.f; ms += mv; }
            if ((g_dmask[i * 3 + jj] >> lane) & 1u) { ds += 1.f; md += mv; }
        }
        #pragma unroll
        for (int o = 16; o; o >>= 1) {
            S  += __shfl_xor_sync(0xffffffffu, S,  o);
            ds += __shfl_xor_sync(0xffffffffu, ds, o);
            ms += __shfl_xor_sync(0xffffffffu, ms, o);
            md += __shfl_xor_sync(0xffffffffu, md, o);
        }
        if (lane == 0) {
            s_rnum[i] = (S - 1.f) * (S * md - ms * ds);
            s_rq[i]   = 0.5f * S * (S - 1.f) * ds;
        }
    }
    if (tid < NN) srow[tid] = g_mat[ianc * NN + tid];
    if (tid >= NN && tid < NN + 3) {
        sm[tid - NN] = g_smask[ianc * 3 + (tid - NN)];
        dm[tid - NN] = g_dmask[ianc * 3 + (tid - NN)];
    }
    __syncthreads();
    if (tid == 0) {   // serial reduce: identical order every block
        float num = 0.f, q = 0.f;
        for (int i = 0; i < NN; i++) { num += s_rnum[i]; q += s_rq[i]; }
        float mean_delta = num / fmaxf(2.f * q, 1.f);
        s_eps = fmaxf(mean_delta * 0.5f, 0.f);   // relu(mean_delta / K_DELTA)
    }
    __syncthreads();
    const float eps = s_eps;

    // cmask for anchor ianc
    for (int p = warp; p < NN; p += 32) {
        unsigned sp = (sm[p >> 5] >> (p & 31)) & 1u;
        float matp = srow[p];
        #pragma unroll
        for (int wd = 0; wd < 3; wd++) {
            float m = srow[wd * 32 + lane] - matp;
            bool cc = sp && (((dm[wd] >> lane) & 1u) != 0u) && (m > 0.f) && (m <= eps);
            unsigned b = __ballot_sync(0xffffffffu, cc);
            if (lane == 0) g_cmask[(ianc * NN + p) * 4 + wd] = b;
        }
    }
}

// ---------------------------------------------------------------------------
// kC: the 340 MB writer. One block per (i,j). Precompute the 96x3 AND-ed
// words into smem; each of 256 threads emits 9 coalesced float4 via
// streaming stores (output >> L2, evict-first).
// ---------------------------------------------------------------------------
__global__ __launch_bounds__(256) void kC_write(float4* __restrict__ out) {
    __shared__ unsigned sw[NN * 3];
    const int r2 = blockIdx.x;           // i*96 + j
    const int j  = r2 % NN;
    const int ibase = r2 - j;            // i*96
    const int tid = threadIdx.x;

    for (int t = tid; t < NN * 3; t += 256) {
        int k  = t / 3;
        int wd = t - k * 3;
        unsigned v = 0u;
        if (k > j)
            v = g_cmask[(r2 << 2) + wd] & g_cmask[((ibase + k) << 2) + wd];
        sw[t] = v;                       // layout sw[k*3 + wd]
    }
    __syncthreads();

    float4* o = out + (size_t)r2 * 2304; // 96*96/4 float4 per (i,j)
    const unsigned ONEF = 0x3f800000u;
    #pragma unroll
    for (int p = 0; p < 9; p++) {
        int pos = p * 256 + tid;         // 0..2303
        int k   = pos / 24;              // 24 float4 per n-row
        int n4  = pos - k * 24;
        unsigned w = sw[k * 3 + (n4 >> 3)];
        unsigned b = w >> ((n4 & 7) * 4);
        float4 v;
        v.x = __uint_as_float(ONEF & (0u - (b & 1u)));
        v.y = __uint_as_float(ONEF & (0u - ((b >> 1) & 1u)));
        v.z = __uint_as_float(ONEF & (0u - ((b >> 2) & 1u)));
        v.w = __uint_as_float(ONEF & (0u - ((b >> 3) & 1u)));
        __stcs(&o[pos], v);              // streaming store: evict-first
    }
}

// ---------------------------------------------------------------------------
extern "C" void kernel_launch(void* const* d_in, const int* in_sizes, int n_in,
                              void* d_out, int out_size) {
    const float* logits = (const float*)d_in[0];   // [96,64]
    const float* labels = (const float*)d_in[1];   // [96,30]

    kAB_prep<<<NN, 1024>>>(logits, labels);
    kC_write<<<NN * NN, 256>>>((float4*)d_out);
}